// round 3
// baseline (speedup 1.0000x reference)
#include <cuda_runtime.h>
#include <math.h>

// Fixed problem shapes
#define BB 8
#define SS 4096
#define HH 1152
#define LL 256
#define HV (HH / 4)    // 288 float4 lanes per row
#define ROWB (HH * 4)  // 4608 bytes per row
#define KK 4
#define NWARP 9
#define CHUNK ((SS + NWARP - 1) / NWARP)   // 456
#define NS 8           // cp.async ring slots
#define DYN_SMEM (NS * ROWB + SS * 4)      // 53248 bytes

__device__ int g_kidx[BB * SS];   // packed: kidx | (pad << 16)

// ---------------------------------------------------------------------------
// cp.async helpers
// ---------------------------------------------------------------------------
__device__ __forceinline__ unsigned smem_u32(const void* p) {
    return (unsigned)__cvta_generic_to_shared(p);
}
__device__ __forceinline__ void cp_async16(unsigned dst, const void* src) {
    asm volatile("cp.async.cg.shared.global [%0], [%1], 16;" :: "r"(dst), "l"(src));
}
__device__ __forceinline__ void cp_commit() {
    asm volatile("cp.async.commit_group;");
}
template <int N>
__device__ __forceinline__ void cp_wait() {
    asm volatile("cp.async.wait_group %0;" :: "n"(N));
}

// ---------------------------------------------------------------------------
// Kernel 1: fused per-batch max_x + kidx computation. Positions stay in regs.
// ---------------------------------------------------------------------------
__global__ __launch_bounds__(512) void prep_kernel(
    const int2* __restrict__ ppi,
    const unsigned char* __restrict__ pad) {
    const int b = blockIdx.x;
    const int t = threadIdx.x;
    __shared__ int smax[16];
    __shared__ int s_factor;

    const int2* p = ppi + (long long)b * SS;
    const unsigned char* pb = pad + (long long)b * SS;

    int2 v[8];
    unsigned char pd[8];
    #pragma unroll
    for (int i = 0; i < 8; i++) v[i] = p[t + i * 512];
    #pragma unroll
    for (int i = 0; i < 8; i++) pd[i] = pb[t + i * 512];

    int mx = 0;
    #pragma unroll
    for (int i = 0; i < 8; i++) mx = max(mx, v[i].x);
    #pragma unroll
    for (int off = 16; off > 0; off >>= 1)
        mx = max(mx, __shfl_xor_sync(0xFFFFFFFFu, mx, off));
    if ((t & 31) == 0) smax[t >> 5] = mx;
    __syncthreads();
    if (t == 0) {
        int m = smax[0];
        #pragma unroll
        for (int i = 1; i < 16; i++) m = max(m, smax[i]);
        if (m < 0) m = 0;
        s_factor = (m + 1) / KK;
    }
    __syncthreads();
    const int factor = s_factor;

    #pragma unroll
    for (int i = 0; i < 8; i++) {
        const int s = t + i * 512;
        int x = max(v[i].x, 0);
        int y = max(v[i].y, 0);
        long long kidx = (long long)(x / KK) + (long long)factor * (long long)(y / KK);
        int ki = (kidx > 0xFFFF || kidx < 0) ? 0xFFFF : (int)kidx;
        g_kidx[(long long)b * SS + s] = ki | (pd[i] ? 0x10000 : 0);
    }
}

// ---------------------------------------------------------------------------
// Kernel 2: one block per (l,b). Ballot-ordered list build, then cp.async
// ring-buffered row accumulation (per-thread pipeline, no syncs).
// ---------------------------------------------------------------------------
__global__ __launch_bounds__(HV) void pool_kernel(
    const float* __restrict__ hs,
    float4* __restrict__ out,
    float* __restrict__ mask,
    float scale) {
    extern __shared__ unsigned char dsm[];
    // layout: [NS row slots][token list]
    int* s_list = (int*)(dsm + NS * ROWB);

    __shared__ int s_wcnt[NWARP];
    __shared__ int s_off[NWARP];
    __shared__ int s_tot_w[NWARP];
    __shared__ int s_cnt, s_total;

    const int l = blockIdx.x;
    const int b = blockIdx.y;
    const int t = threadIdx.x;
    const int w = t >> 5;
    const int lane = t & 31;
    const unsigned lt = (1u << lane) - 1u;

    const int* kb = g_kidx + b * SS;
    const int begin = w * CHUNK;
    const int end = min(begin + CHUNK, SS);

    // Pass 1: count matches
    int c_np = 0, c_tot = 0;
    #pragma unroll 4
    for (int sb = begin; sb < end; sb += 32) {
        const int s = sb + lane;
        const int v = (s < end) ? kb[s] : -1;
        const bool m = ((v & 0xFFFF) == l);
        const unsigned bt = __ballot_sync(0xFFFFFFFFu, m);
        const unsigned bn = __ballot_sync(0xFFFFFFFFu, m && !(v & 0x10000));
        c_tot += __popc(bt);
        c_np += __popc(bn);
    }
    if (lane == 0) { s_wcnt[w] = c_np; s_tot_w[w] = c_tot; }
    __syncthreads();
    if (t == 0) {
        int acc = 0, tot = 0;
        #pragma unroll
        for (int i = 0; i < NWARP; i++) {
            s_off[i] = acc;
            acc += s_wcnt[i];
            tot += s_tot_w[i];
        }
        s_cnt = acc;
        s_total = tot;
    }
    __syncthreads();

    // Pass 2: ordered compaction (sorted by s -> deterministic FP order)
    int off = s_off[w];
    #pragma unroll 4
    for (int sb = begin; sb < end; sb += 32) {
        const int s = sb + lane;
        const int v = (s < end) ? kb[s] : -1;
        const bool m = ((v & 0xFFFF) == l) && !(v & 0x10000);
        const unsigned bn = __ballot_sync(0xFFFFFFFFu, m);
        if (m) s_list[off + __popc(bn & lt)] = s;
        off += __popc(bn);
    }
    __syncthreads();
    const int cnt = s_cnt;

    // cp.async ring accumulate. Thread t owns 16 bytes (lane t) of every row:
    // it copies them, waits on its own groups, reads only bytes it copied.
    const char* gbase = (const char*)hs + (long long)b * SS * ROWB + (long long)t * 16;
    const unsigned slot_base = smem_u32(dsm) + (unsigned)t * 16;

    int head = 0;
    const int pre = min(cnt, NS);
    for (; head < pre; head++) {
        cp_async16(slot_base + (unsigned)(head % NS) * ROWB,
                   gbase + (long long)s_list[head] * ROWB);
        cp_commit();
    }

    float4 a0 = make_float4(0.f, 0.f, 0.f, 0.f);
    float4 a1 = a0;
    for (int i = 0; i < cnt; i++) {
        if (head < cnt) cp_wait<NS - 1>(); else cp_wait<0>();
        const float4 x = *(const float4*)(dsm + (i % NS) * ROWB + t * 16);
        if (i & 1) { a1.x += x.x; a1.y += x.y; a1.z += x.z; a1.w += x.w; }
        else       { a0.x += x.x; a0.y += x.y; a0.z += x.z; a0.w += x.w; }
        if (head < cnt) {
            cp_async16(slot_base + (unsigned)(head % NS) * ROWB,
                       gbase + (long long)s_list[head] * ROWB);
            cp_commit();
            head++;
        }
    }

    float4 r;
    r.x = (a0.x + a1.x) * scale;
    r.y = (a0.y + a1.y) * scale;
    r.z = (a0.z + a1.z) * scale;
    r.w = (a0.w + a1.w) * scale;
    out[((long long)b * LL + l) * HV + t] = r;

    if (t == 0 && mask != nullptr)
        mask[(long long)b * LL + l] = (s_total > 0) ? 1.0f : 0.0f;
}

// ---------------------------------------------------------------------------
// Launch
// ---------------------------------------------------------------------------
extern "C" void kernel_launch(void* const* d_in, const int* in_sizes, int n_in,
                              void* d_out, int out_size) {
    const float*         hs  = (const float*)d_in[0];
    const int2*          ppi = (const int2*)d_in[1];
    const unsigned char* pad = (const unsigned char*)d_in[2];

    const float scale = sqrtf((float)HH) / (float)(KK * KK);

    cudaFuncSetAttribute(pool_kernel,
                         cudaFuncAttributeMaxDynamicSharedMemorySize, DYN_SMEM);

    prep_kernel<<<BB, 512>>>(ppi, pad);

    float* out  = (float*)d_out;
    float* mask = nullptr;
    const long long pooled_elems = (long long)BB * LL * HH;
    if ((long long)out_size >= pooled_elems + (long long)BB * LL)
        mask = out + pooled_elems;

    pool_kernel<<<dim3(LL, BB), HV, DYN_SMEM>>>(hs, (float4*)out, mask, scale);
}

// round 4
// speedup vs baseline: 1.1282x; 1.1282x over previous
#include <cuda_runtime.h>
#include <math.h>

// Fixed problem shapes
#define BB 8
#define SS 4096
#define HH 1152
#define LL 256
#define HV (HH / 4)    // 288 float4 lanes per row
#define KK 4

// Scratch (L2-resident)
__device__ int g_off[BB * LL];     // CSR offsets (exclusive) into g_tok
__device__ int g_cnt[BB * LL];     // non-pad count per bucket
__device__ int g_tok[BB * SS];     // token lists (non-pad tokens only)

// ---------------------------------------------------------------------------
// Kernel 1: per batch — max_x, kidx, CSR inverted index, mask.
// One block of 512 threads per batch; all token data loaded to regs up front.
// ---------------------------------------------------------------------------
__global__ __launch_bounds__(512) void prep_kernel(
    const int2* __restrict__ ppi,
    const unsigned char* __restrict__ pad,
    float* __restrict__ mask) {
    const int b = blockIdx.x;
    const int t = threadIdx.x;

    __shared__ int smax[16];
    __shared__ int s_factor;
    __shared__ int c_np[LL];    // non-pad counts
    __shared__ int c_all[LL];   // all-match counts (for mask)
    __shared__ int s_ofs[LL];   // exclusive scan of c_np
    __shared__ int s_cur[LL];   // scatter cursors
    __shared__ int s_scan[LL];  // scan workspace

    const int2* p = ppi + (long long)b * SS;
    const unsigned char* pb = pad + (long long)b * SS;

    int2 v[8];
    unsigned char pd[8];
    #pragma unroll
    for (int i = 0; i < 8; i++) v[i] = p[t + i * 512];
    #pragma unroll
    for (int i = 0; i < 8; i++) pd[i] = pb[t + i * 512];

    // max_x reduction
    int mx = 0;
    #pragma unroll
    for (int i = 0; i < 8; i++) mx = max(mx, v[i].x);
    #pragma unroll
    for (int off = 16; off > 0; off >>= 1)
        mx = max(mx, __shfl_xor_sync(0xFFFFFFFFu, mx, off));
    if ((t & 31) == 0) smax[t >> 5] = mx;
    if (t < LL) { c_np[t] = 0; c_all[t] = 0; s_cur[t] = 0; }
    __syncthreads();
    if (t == 0) {
        int m = smax[0];
        #pragma unroll
        for (int i = 1; i < 16; i++) m = max(m, smax[i]);
        if (m < 0) m = 0;
        s_factor = (m + 1) / KK;
    }
    __syncthreads();
    const int factor = s_factor;

    // kidx + counts
    int ki[8];
    #pragma unroll
    for (int i = 0; i < 8; i++) {
        int x = max(v[i].x, 0);
        int y = max(v[i].y, 0);
        long long kv = (long long)(x / KK) + (long long)factor * (long long)(y / KK);
        ki[i] = (kv >= 0 && kv < LL) ? (int)kv : -1;
        if (ki[i] >= 0) {
            atomicAdd(&c_all[ki[i]], 1);
            if (!pd[i]) atomicAdd(&c_np[ki[i]], 1);
        }
    }
    __syncthreads();

    // exclusive scan of c_np over 256 buckets (Hillis-Steele, threads 0..255)
    if (t < LL) s_scan[t] = c_np[t];
    __syncthreads();
    #pragma unroll
    for (int d = 1; d < LL; d <<= 1) {
        int val = 0;
        if (t < LL && t >= d) val = s_scan[t - d];
        __syncthreads();
        if (t < LL) s_scan[t] += val;
        __syncthreads();
    }
    if (t < LL) {
        const int excl = s_scan[t] - c_np[t];
        s_ofs[t] = excl;
        g_off[b * LL + t] = excl;
        g_cnt[b * LL + t] = c_np[t];
        if (mask != nullptr)
            mask[(long long)b * LL + t] = (c_all[t] > 0) ? 1.0f : 0.0f;
    }
    __syncthreads();

    // scatter non-pad tokens (order within bucket nondet; pool sorts)
    #pragma unroll
    for (int i = 0; i < 8; i++) {
        if (ki[i] >= 0 && !pd[i]) {
            const int pos = s_ofs[ki[i]] + atomicAdd(&s_cur[ki[i]], 1);
            g_tok[b * SS + pos] = t + i * 512;
        }
    }
}

// ---------------------------------------------------------------------------
// Kernel 2: one block per (l,b). Load tiny CSR list, sort, accumulate rows.
// ---------------------------------------------------------------------------
__global__ __launch_bounds__(HV) void pool_kernel(
    const float4* __restrict__ hs,
    float4* __restrict__ out,
    float scale) {
    const int l = blockIdx.x;
    const int b = blockIdx.y;
    const int t = threadIdx.x;
    const int bl = b * LL + l;

    __shared__ int s_list[SS];

    const int off = g_off[bl];
    const int cnt = g_cnt[bl];

    for (int i = t; i < cnt; i += HV)
        s_list[i] = g_tok[b * SS + off + i];
    __syncthreads();

    // canonical order for deterministic FP summation (typical cnt = 16)
    if (t == 0 && cnt > 1 && cnt <= 64) {
        for (int i = 1; i < cnt; i++) {
            const int key = s_list[i];
            int j = i - 1;
            while (j >= 0 && s_list[j] > key) { s_list[j + 1] = s_list[j]; j--; }
            s_list[j + 1] = key;
        }
    }
    __syncthreads();

    const float4* base = hs + (long long)b * SS * HV + t;
    float4 a0 = make_float4(0.f, 0.f, 0.f, 0.f);
    float4 a1 = a0, a2 = a0, a3 = a0;
    int i = 0;
    for (; i + 4 <= cnt; i += 4) {
        const int q0 = s_list[i], q1 = s_list[i + 1];
        const int q2 = s_list[i + 2], q3 = s_list[i + 3];
        const float4 x0 = __ldg(base + (long long)q0 * HV);
        const float4 x1 = __ldg(base + (long long)q1 * HV);
        const float4 x2 = __ldg(base + (long long)q2 * HV);
        const float4 x3 = __ldg(base + (long long)q3 * HV);
        a0.x += x0.x; a0.y += x0.y; a0.z += x0.z; a0.w += x0.w;
        a1.x += x1.x; a1.y += x1.y; a1.z += x1.z; a1.w += x1.w;
        a2.x += x2.x; a2.y += x2.y; a2.z += x2.z; a2.w += x2.w;
        a3.x += x3.x; a3.y += x3.y; a3.z += x3.z; a3.w += x3.w;
    }
    for (; i < cnt; i++) {
        const float4 x = __ldg(base + (long long)s_list[i] * HV);
        a0.x += x.x; a0.y += x.y; a0.z += x.z; a0.w += x.w;
    }
    float4 r;
    r.x = ((a0.x + a1.x) + (a2.x + a3.x)) * scale;
    r.y = ((a0.y + a1.y) + (a2.y + a3.y)) * scale;
    r.z = ((a0.z + a1.z) + (a2.z + a3.z)) * scale;
    r.w = ((a0.w + a1.w) + (a2.w + a3.w)) * scale;
    out[((long long)bl) * HV + t] = r;
}

// ---------------------------------------------------------------------------
// Launch
// ---------------------------------------------------------------------------
extern "C" void kernel_launch(void* const* d_in, const int* in_sizes, int n_in,
                              void* d_out, int out_size) {
    const float*         hs  = (const float*)d_in[0];
    const int2*          ppi = (const int2*)d_in[1];
    const unsigned char* pad = (const unsigned char*)d_in[2];

    const float scale = sqrtf((float)HH) / (float)(KK * KK);

    float* out  = (float*)d_out;
    float* mask = nullptr;
    const long long pooled_elems = (long long)BB * LL * HH;
    if ((long long)out_size >= pooled_elems + (long long)BB * LL)
        mask = out + pooled_elems;

    prep_kernel<<<BB, 512>>>(ppi, pad, mask);
    pool_kernel<<<dim3(LL, BB), HV>>>((const float4*)hs, (float4*)out, scale);
}

// round 5
// speedup vs baseline: 1.3906x; 1.2326x over previous
#include <cuda_runtime.h>
#include <math.h>

// Fixed problem shapes
#define BB 8
#define SS 4096
#define HH 1152
#define LL 256
#define HV (HH / 4)    // 288 float4 lanes per row
#define KK 4

// Scratch (L2-resident)
__device__ int2 g_meta[BB * LL];   // (offset, non-pad count) per bucket
__device__ int  g_tok[BB * SS];    // token lists (non-pad tokens only)

// ---------------------------------------------------------------------------
// Kernel 1: per batch — max_x, kidx, CSR inverted index, mask.
// ---------------------------------------------------------------------------
__global__ __launch_bounds__(512) void prep_kernel(
    const int2* __restrict__ ppi,
    const unsigned char* __restrict__ pad,
    float* __restrict__ mask) {
    const int b = blockIdx.x;
    const int t = threadIdx.x;
    const int lane = t & 31;
    const int w = t >> 5;

    __shared__ int smax[16];
    __shared__ int s_factor;
    __shared__ int c_np[LL];
    __shared__ int c_all[LL];
    __shared__ int s_ofs[LL];
    __shared__ int s_cur[LL];
    __shared__ int s_wsum[8];

    const int2* p = ppi + (long long)b * SS;
    const unsigned char* pb = pad + (long long)b * SS;

    int2 v[8];
    unsigned char pd[8];
    #pragma unroll
    for (int i = 0; i < 8; i++) v[i] = p[t + i * 512];
    #pragma unroll
    for (int i = 0; i < 8; i++) pd[i] = pb[t + i * 512];

    // max_x reduction
    int mx = 0;
    #pragma unroll
    for (int i = 0; i < 8; i++) mx = max(mx, v[i].x);
    #pragma unroll
    for (int off = 16; off > 0; off >>= 1)
        mx = max(mx, __shfl_xor_sync(0xFFFFFFFFu, mx, off));
    if (lane == 0) smax[w] = mx;
    if (t < LL) { c_np[t] = 0; c_all[t] = 0; s_cur[t] = 0; }
    __syncthreads();
    if (t == 0) {
        int m = smax[0];
        #pragma unroll
        for (int i = 1; i < 16; i++) m = max(m, smax[i]);
        if (m < 0) m = 0;
        s_factor = (m + 1) / KK;
    }
    __syncthreads();
    const int factor = s_factor;

    // kidx + counts
    int ki[8];
    #pragma unroll
    for (int i = 0; i < 8; i++) {
        int x = max(v[i].x, 0);
        int y = max(v[i].y, 0);
        long long kv = (long long)(x / KK) + (long long)factor * (long long)(y / KK);
        ki[i] = (kv >= 0 && kv < LL) ? (int)kv : -1;
        if (ki[i] >= 0) {
            atomicAdd(&c_all[ki[i]], 1);
            if (!pd[i]) atomicAdd(&c_np[ki[i]], 1);
        }
    }
    __syncthreads();

    // exclusive scan of c_np over 256 buckets: warp scans + offsets (3 barriers)
    int myc = 0, inc = 0;
    if (t < LL) {
        myc = c_np[t];
        inc = myc;
        #pragma unroll
        for (int d = 1; d < 32; d <<= 1) {
            int up = __shfl_up_sync(0xFFFFFFFFu, inc, d);
            if (lane >= d) inc += up;
        }
        if (lane == 31) s_wsum[w] = inc;
    }
    __syncthreads();
    if (t == 0) {
        int run = 0;
        #pragma unroll
        for (int i = 0; i < 8; i++) { int x = s_wsum[i]; s_wsum[i] = run; run += x; }
    }
    __syncthreads();
    if (t < LL) {
        const int excl = inc - myc + s_wsum[w];
        s_ofs[t] = excl;
        g_meta[b * LL + t] = make_int2(excl, myc);
        if (mask != nullptr)
            mask[(long long)b * LL + t] = (c_all[t] > 0) ? 1.0f : 0.0f;
    }
    __syncthreads();

    // scatter non-pad tokens (order nondet; pool rank-orders)
    #pragma unroll
    for (int i = 0; i < 8; i++) {
        if (ki[i] >= 0 && !pd[i]) {
            const int pos = s_ofs[ki[i]] + atomicAdd(&s_cur[ki[i]], 1);
            g_tok[b * SS + pos] = t + i * 512;
        }
    }
}

// ---------------------------------------------------------------------------
// Kernel 2: one block per (l,b). Load list, parallel rank-order, accumulate.
// ---------------------------------------------------------------------------
__global__ __launch_bounds__(HV) void pool_kernel(
    const float4* __restrict__ hs,
    float4* __restrict__ out,
    float scale) {
    const int l = blockIdx.x;
    const int b = blockIdx.y;
    const int t = threadIdx.x;
    const int bl = b * LL + l;

    __shared__ int s_list[SS];
    __shared__ int s_sort[SS];

    const int2 meta = g_meta[bl];
    const int off = meta.x;
    const int cnt = meta.y;

    for (int i = t; i < cnt; i += HV)
        s_list[i] = g_tok[b * SS + off + i];
    __syncthreads();

    // parallel rank ordering -> deterministic ascending order in s_sort
    for (int base = 0; base < cnt; base += HV) {
        const int i = base + t;
        if (i < cnt) {
            const int val = s_list[i];
            int r = 0;
            for (int j = 0; j < cnt; j++) r += (s_list[j] < val);
            s_sort[r] = val;
        }
    }
    __syncthreads();

    // 4-way unrolled coalesced row accumulation
    const float4* base4 = hs + (long long)b * SS * HV + t;
    float4 a0 = make_float4(0.f, 0.f, 0.f, 0.f);
    float4 a1 = a0, a2 = a0, a3 = a0;
    int i = 0;
    for (; i + 4 <= cnt; i += 4) {
        const int q0 = s_sort[i], q1 = s_sort[i + 1];
        const int q2 = s_sort[i + 2], q3 = s_sort[i + 3];
        const float4 x0 = __ldg(base4 + (long long)q0 * HV);
        const float4 x1 = __ldg(base4 + (long long)q1 * HV);
        const float4 x2 = __ldg(base4 + (long long)q2 * HV);
        const float4 x3 = __ldg(base4 + (long long)q3 * HV);
        a0.x += x0.x; a0.y += x0.y; a0.z += x0.z; a0.w += x0.w;
        a1.x += x1.x; a1.y += x1.y; a1.z += x1.z; a1.w += x1.w;
        a2.x += x2.x; a2.y += x2.y; a2.z += x2.z; a2.w += x2.w;
        a3.x += x3.x; a3.y += x3.y; a3.z += x3.z; a3.w += x3.w;
    }
    for (; i < cnt; i++) {
        const float4 x = __ldg(base4 + (long long)s_sort[i] * HV);
        a0.x += x.x; a0.y += x.y; a0.z += x.z; a0.w += x.w;
    }
    float4 r;
    r.x = ((a0.x + a1.x) + (a2.x + a3.x)) * scale;
    r.y = ((a0.y + a1.y) + (a2.y + a3.y)) * scale;
    r.z = ((a0.z + a1.z) + (a2.z + a3.z)) * scale;
    r.w = ((a0.w + a1.w) + (a2.w + a3.w)) * scale;
    out[((long long)bl) * HV + t] = r;
}

// ---------------------------------------------------------------------------
// Launch
// ---------------------------------------------------------------------------
extern "C" void kernel_launch(void* const* d_in, const int* in_sizes, int n_in,
                              void* d_out, int out_size) {
    const float*         hs  = (const float*)d_in[0];
    const int2*          ppi = (const int2*)d_in[1];
    const unsigned char* pad = (const unsigned char*)d_in[2];

    const float scale = sqrtf((float)HH) / (float)(KK * KK);

    float* out  = (float*)d_out;
    float* mask = nullptr;
    const long long pooled_elems = (long long)BB * LL * HH;
    if ((long long)out_size >= pooled_elems + (long long)BB * LL)
        mask = out + pooled_elems;

    prep_kernel<<<BB, 512>>>(ppi, pad, mask);
    pool_kernel<<<dim3(LL, BB), HV>>>((const float4*)hs, (float4*)out, scale);
}